// round 1
// baseline (speedup 1.0000x reference)
#include <cuda_runtime.h>
#include <cuda_fp16.h>
#include <cstdint>

// Problem constants
#define N_    32
#define C_    128
#define H_    56
#define W_    56
#define K_    256
#define HW_   3136      // 56*56
#define PIX_  100352    // 32*3136
#define KIN_  1152      // 128*9

// GEMM tiling
#define BM    128
#define BN    128
#define BK    32
#define NSTEP 36        // 1152/32
#define SPITCH 40       // BK + 8 halves -> conflict-free fragment loads

// Scratch: quantized fp16 input / weights (allocation-free rule -> __device__ globals)
__device__ alignas(16) __half g_xq[N_ * C_ * HW_];
__device__ alignas(16) __half g_wq[K_ * KIN_];

__device__ __forceinline__ float quant16f(float x) {
    // round half-to-even like jnp.round, clip to int16 range, 12 frac bits
    float r = rintf(x * 4096.0f);
    r = fminf(fmaxf(r, -32768.0f), 32767.0f);
    return r * (1.0f / 4096.0f);
}

__global__ void quant_x_kernel(const float4* __restrict__ in, int n4) {
    int i = blockIdx.x * blockDim.x + threadIdx.x;
    if (i >= n4) return;
    float4 v = in[i];
    __half2* o = reinterpret_cast<__half2*>(g_xq);
    o[2 * i]     = __floats2half2_rn(quant16f(v.x), quant16f(v.y));
    o[2 * i + 1] = __floats2half2_rn(quant16f(v.z), quant16f(v.w));
}

__global__ void quant_w_kernel(const float4* __restrict__ in, int n4) {
    int i = blockIdx.x * blockDim.x + threadIdx.x;
    if (i >= n4) return;
    float4 v = in[i];
    __half2* o = reinterpret_cast<__half2*>(g_wq);
    o[2 * i]     = __floats2half2_rn(quant16f(v.x), quant16f(v.y));
    o[2 * i + 1] = __floats2half2_rn(quant16f(v.z), quant16f(v.w));
}

// Implicit-GEMM conv: out[k, p] = sum_t wq[k, t] * im2col(xq)[t, p]
//   t = c*9 + r*3 + s   (contiguous in wq's OIHW layout)
//   p = n*3136 + h*56 + w
__global__ __launch_bounds__(256) void conv_mma_kernel(float* __restrict__ out) {
    __shared__ __half As[2][BM][SPITCH];   // [buf][m][k]  (weights)
    __shared__ __half Bs[2][BN][SPITCH];   // [buf][p][k]  (im2col input)

    const int tid  = threadIdx.x;
    const int lane = tid & 31;
    const int wid  = tid >> 5;
    const int warpM = wid & 3;   // 4 warps along M
    const int warpN = wid >> 2;  // 2 warps along N
    const int g  = lane >> 2;    // groupID
    const int tg = lane & 3;     // thread-in-group

    const int p0 = blockIdx.x * BN;
    const int k0 = blockIdx.y * BM;

    // ---- A (weight) tile load mapping: vectorized, contiguous in t ----
    const int aRow = tid >> 1;                // 0..127
    const int aCol = (tid & 1) << 4;          // 0 or 16
    const __half* aSrc = g_wq + (size_t)(k0 + aRow) * KIN_ + aCol;

    // ---- B (im2col) tile load mapping: one pixel per thread-pair ----
    const int pp = tid & 127;                 // local pixel
    const int tb = tid >> 7;                  // 0 or 1: which t parity
    const unsigned p = (unsigned)(p0 + pp);
    const unsigned n  = p / HW_;
    const unsigned hw = p % HW_;
    const int h = (int)(hw / W_);
    const int w = (int)(hw % W_);
    // x index = xbase + c*3136 + r*56 + s  (derivation: pad-1 window)
    const int xbase = (int)n * (C_ * HW_) + h * W_ + w - 57;
    // halo validity masks per r / s
    const unsigned vr = (h >= 1 ? 1u : 0u) | 2u | (h <= H_ - 2 ? 4u : 0u);
    const unsigned vs = (w >= 1 ? 1u : 0u) | 2u | (w <= W_ - 2 ? 4u : 0u);

    float acc[2][8][4];
    #pragma unroll
    for (int i = 0; i < 2; ++i)
        #pragma unroll
        for (int j = 0; j < 8; ++j)
            #pragma unroll
            for (int e = 0; e < 4; ++e) acc[i][j][e] = 0.0f;

    uint4 av0, av1;
    __half bv[16];

    auto loadG = [&](int step) {
        const __half* sa = aSrc + step * BK;
        av0 = *reinterpret_cast<const uint4*>(sa);
        av1 = *reinterpret_cast<const uint4*>(sa + 8);
        const int tstep = step * BK + tb;
        #pragma unroll
        for (int j = 0; j < 16; ++j) {
            int t  = tstep + 2 * j;
            int c  = (int)((unsigned)t / 9u);
            int rs = t - 9 * c;
            int r  = (rs * 11) >> 5;       // rs/3 for rs<9
            int s  = rs - 3 * r;
            bool ok = ((vr >> r) & (vs >> s) & 1u) != 0u;
            __half v = __ushort_as_half((unsigned short)0);
            if (ok) v = g_xq[xbase + c * HW_ + r * W_ + s];
            bv[j] = v;
        }
    };

    auto storeS = [&](int buf) {
        *reinterpret_cast<uint4*>(&As[buf][aRow][aCol])     = av0;
        *reinterpret_cast<uint4*>(&As[buf][aRow][aCol + 8]) = av1;
        #pragma unroll
        for (int j = 0; j < 16; ++j)
            Bs[buf][pp][tb + 2 * j] = bv[j];
    };

    auto compute = [&](int buf) {
        #pragma unroll
        for (int kk = 0; kk < 2; ++kk) {
            uint32_t a[2][4], b[8][2];
            const int kc = kk * 16 + tg * 2;
            #pragma unroll
            for (int i = 0; i < 2; ++i) {
                const int m = warpM * 32 + i * 16;
                a[i][0] = *reinterpret_cast<const uint32_t*>(&As[buf][m + g][kc]);
                a[i][1] = *reinterpret_cast<const uint32_t*>(&As[buf][m + g + 8][kc]);
                a[i][2] = *reinterpret_cast<const uint32_t*>(&As[buf][m + g][kc + 8]);
                a[i][3] = *reinterpret_cast<const uint32_t*>(&As[buf][m + g + 8][kc + 8]);
            }
            #pragma unroll
            for (int j = 0; j < 8; ++j) {
                const int pc = warpN * 64 + j * 8 + g;
                b[j][0] = *reinterpret_cast<const uint32_t*>(&Bs[buf][pc][kc]);
                b[j][1] = *reinterpret_cast<const uint32_t*>(&Bs[buf][pc][kc + 8]);
            }
            #pragma unroll
            for (int i = 0; i < 2; ++i)
                #pragma unroll
                for (int j = 0; j < 8; ++j)
                    asm volatile(
                        "mma.sync.aligned.m16n8k16.row.col.f32.f16.f16.f32 "
                        "{%0,%1,%2,%3}, {%4,%5,%6,%7}, {%8,%9}, {%0,%1,%2,%3};\n"
                        : "+f"(acc[i][j][0]), "+f"(acc[i][j][1]),
                          "+f"(acc[i][j][2]), "+f"(acc[i][j][3])
                        : "r"(a[i][0]), "r"(a[i][1]), "r"(a[i][2]), "r"(a[i][3]),
                          "r"(b[j][0]), "r"(b[j][1]));
        }
    };

    // Prologue
    loadG(0);
    storeS(0);
    __syncthreads();

    #pragma unroll 1
    for (int step = 0; step < NSTEP; ++step) {
        const int cur = step & 1;
        if (step + 1 < NSTEP) loadG(step + 1);   // LDGs in flight during compute
        compute(cur);
        if (step + 1 < NSTEP) storeS(cur ^ 1);
        __syncthreads();
    }

    // Epilogue: out idx = p + 3136*(255*n + k)
    #pragma unroll
    for (int i = 0; i < 2; ++i) {
        const int kb = k0 + warpM * 32 + i * 16 + g;
        #pragma unroll
        for (int j = 0; j < 8; ++j) {
            const int pc = p0 + warpN * 64 + j * 8 + tg * 2;
            #pragma unroll
            for (int e = 0; e < 2; ++e) {
                const unsigned pe = (unsigned)(pc + e);
                const unsigned nn = pe / HW_;
                out[pe + (size_t)HW_ * (255u * nn + (unsigned)kb)]       = acc[i][j][e];
                out[pe + (size_t)HW_ * (255u * nn + (unsigned)(kb + 8))] = acc[i][j][2 + e];
            }
        }
    }
}

extern "C" void kernel_launch(void* const* d_in, const int* in_sizes, int n_in,
                              void* d_out, int out_size) {
    const float* x   = (const float*)d_in[0];   // (32,128,56,56) f32
    const float* wgt = (const float*)d_in[1];   // (256,128,3,3)  f32

    const int nx4 = (N_ * C_ * HW_) / 4;        // 3211264
    const int nw4 = (K_ * KIN_) / 4;            // 73728

    quant_x_kernel<<<(nx4 + 255) / 256, 256>>>((const float4*)x, nx4);
    quant_w_kernel<<<(nw4 + 255) / 256, 256>>>((const float4*)wgt, nw4);

    dim3 grid(PIX_ / BN, K_ / BM);              // (784, 2)
    conv_mma_kernel<<<grid, 256>>>((float*)d_out);
}

// round 2
// speedup vs baseline: 1.0751x; 1.0751x over previous
#include <cuda_runtime.h>
#include <cuda_fp16.h>
#include <cstdint>

// Problem constants
#define N_    32
#define C_    128
#define H_    56
#define W_    56
#define K_    256
#define HW_   3136      // 56*56
#define PIX_  100352    // 32*3136
#define KINP  1152      // 128*9
#define HP_   58        // padded H
#define WP_   58        // padded W

// GEMM tiling
#define BM    128
#define BN    128
#define BK    32
#define NSTEP 36        // 1152/32  (9 rs positions x 4 channel blocks)
#define SPITCH 40       // BK + 8 halves -> conflict-free fragment loads

// Scratch (allocation-free rule -> __device__ globals)
// Padded NHWC quantized input: [N][58][58][C] fp16
__device__ alignas(16) __half g_xp[(size_t)N_ * HP_ * WP_ * C_];
// Packed quantized weights: [k][rs*128 + c] fp16  (rs-major, c-minor)
__device__ alignas(16) __half g_wq[K_ * KINP];

__device__ __forceinline__ float quant16f(float x) {
    float r = rintf(x * 4096.0f);               // round-half-even like jnp.round
    r = fminf(fmaxf(r, -32768.0f), 32767.0f);
    return r * (1.0f / 4096.0f);
}

// ---- zero the padded borders of g_xp (rows h=0,57; cols w=0,57) ----
__global__ void zero_border_kernel() {
    int b = blockIdx.x;              // 32*58
    int n = b / HP_, hp = b % HP_;
    __half* rowp = g_xp + ((size_t)(n * HP_ + hp)) * WP_ * C_;
    uint4 z = make_uint4(0, 0, 0, 0);
    if (hp == 0 || hp == HP_ - 1) {
        for (int i = threadIdx.x; i < WP_ * C_ / 8; i += blockDim.x)
            reinterpret_cast<uint4*>(rowp)[i] = z;
    } else {
        if (threadIdx.x < 32) {
            int side = threadIdx.x >> 4;               // 0: w=0, 1: w=57
            int q    = threadIdx.x & 15;               // 16 x uint4 = 128 halves
            __half* colp = rowp + (side ? (size_t)(WP_ - 1) * C_ : 0);
            reinterpret_cast<uint4*>(colp)[q] = z;
        }
    }
}

// ---- quantize + transpose x: NCHW fp32 -> padded NHWC fp16 ----
// grid (N, H), 256 threads. Block handles one (n,h) slab: 128c x 56w.
__global__ void xform_x_kernel(const float* __restrict__ x) {
    __shared__ __half st[W_ * C_];   // [w][c], 14 KB
    const int n = blockIdx.x, h = blockIdx.y;
    const int tid = threadIdx.x;
    const int c  = tid >> 1;
    const int wh = (tid & 1) * 28;
    const float* src = x + ((size_t)(n * C_ + c) * H_ + h) * W_ + wh;
    #pragma unroll
    for (int j = 0; j < 7; ++j) {
        float4 v = *reinterpret_cast<const float4*>(src + 4 * j);
        int wb = wh + 4 * j;
        st[(wb + 0) * C_ + c] = __float2half_rn(quant16f(v.x));
        st[(wb + 1) * C_ + c] = __float2half_rn(quant16f(v.y));
        st[(wb + 2) * C_ + c] = __float2half_rn(quant16f(v.z));
        st[(wb + 3) * C_ + c] = __float2half_rn(quant16f(v.w));
    }
    __syncthreads();
    // write interior: padded (h+1, w+1), vectorized 16B
    __half* dst = g_xp + ((size_t)((n * HP_ + h + 1) * WP_ + 1)) * C_;
    for (int idx = tid; idx < W_ * C_ / 8; idx += 256) {
        int w = idx >> 4, q = idx & 15;
        reinterpret_cast<uint4*>(dst + (size_t)w * C_)[q] =
            reinterpret_cast<const uint4*>(st + w * C_)[q];
    }
}

// ---- quantize + pack weights: OIHW -> [k][rs*128+c] ----
__global__ void quant_w_kernel(const float* __restrict__ w) {
    int idx = blockIdx.x * 256 + threadIdx.x;
    if (idx >= K_ * KINP) return;
    int k = idx / KINP, t = idx % KINP;
    int rs = t >> 7, c = t & 127;
    float v = w[(size_t)(k * C_ + c) * 9 + rs];
    g_wq[idx] = __float2half_rn(quant16f(v));
}

// ---- implicit-GEMM conv with mma.sync ----
// out[k, p] = sum_t g_wq[k, t] * B[t, p],  t = rs*128+c,
// B[t, p] = g_xp[n, h+r, w+s, c]  (pure contiguous loads thanks to padding)
__global__ __launch_bounds__(256, 2) void conv_mma_kernel(float* __restrict__ out) {
    __shared__ __half As[2][BM][SPITCH];   // [buf][k-row][k-local]  (weights)
    __shared__ __half Bs[2][BN][SPITCH];   // [buf][pixel][k-local]  (input)

    const int tid  = threadIdx.x;
    const int lane = tid & 31;
    const int wid  = tid >> 5;
    const int warpM = wid & 3;   // 4 warps along M
    const int warpN = wid >> 2;  // 2 warps along N
    const int g  = lane >> 2;
    const int tg = lane & 3;

    const int p0 = blockIdx.x * BN;
    const int k0 = blockIdx.y * BM;

    const int row128 = tid & 127;
    const int hi16   = (tid >> 7) << 4;    // 0 or 16 (half-chunk within BK)

    // A source: packed weights, contiguous in t
    const __half* aSrc = g_wq + (size_t)(k0 + row128) * KINP + hi16;

    // B source: per-pixel base into padded NHWC buffer
    const int p  = p0 + row128;
    const int n  = p / HW_;
    const int hw = p % HW_;
    const int h  = hw / W_;
    const int w  = hw % W_;
    const __half* bBase = g_xp + ((size_t)((n * HP_ + h) * WP_ + w)) * C_ + hi16;

    float acc[2][8][4];
    #pragma unroll
    for (int i = 0; i < 2; ++i)
        #pragma unroll
        for (int j = 0; j < 8; ++j)
            #pragma unroll
            for (int e = 0; e < 4; ++e) acc[i][j][e] = 0.0f;

    uint4 av0, av1, bv0, bv1;

    auto loadG = [&](int step) {
        const __half* sa = aSrc + step * BK;
        av0 = *reinterpret_cast<const uint4*>(sa);
        av1 = *reinterpret_cast<const uint4*>(sa + 8);
        const int rs = step >> 2;
        const int r  = (rs * 11) >> 5;     // rs/3 for rs<9
        const int s  = rs - 3 * r;
        const __half* sb = bBase + (r * WP_ + s) * C_ + (step & 3) * BK;
        bv0 = *reinterpret_cast<const uint4*>(sb);
        bv1 = *reinterpret_cast<const uint4*>(sb + 8);
    };

    auto storeS = [&](int buf) {
        *reinterpret_cast<uint4*>(&As[buf][row128][hi16])     = av0;
        *reinterpret_cast<uint4*>(&As[buf][row128][hi16 + 8]) = av1;
        *reinterpret_cast<uint4*>(&Bs[buf][row128][hi16])     = bv0;
        *reinterpret_cast<uint4*>(&Bs[buf][row128][hi16 + 8]) = bv1;
    };

    auto compute = [&](int buf) {
        #pragma unroll
        for (int kk = 0; kk < 2; ++kk) {
            uint32_t a[2][4], b[8][2];
            const int kc = kk * 16 + tg * 2;
            #pragma unroll
            for (int i = 0; i < 2; ++i) {
                const int m = warpM * 32 + i * 16;
                a[i][0] = *reinterpret_cast<const uint32_t*>(&As[buf][m + g][kc]);
                a[i][1] = *reinterpret_cast<const uint32_t*>(&As[buf][m + g + 8][kc]);
                a[i][2] = *reinterpret_cast<const uint32_t*>(&As[buf][m + g][kc + 8]);
                a[i][3] = *reinterpret_cast<const uint32_t*>(&As[buf][m + g + 8][kc + 8]);
            }
            #pragma unroll
            for (int j = 0; j < 8; ++j) {
                const int pc = warpN * 64 + j * 8 + g;
                b[j][0] = *reinterpret_cast<const uint32_t*>(&Bs[buf][pc][kc]);
                b[j][1] = *reinterpret_cast<const uint32_t*>(&Bs[buf][pc][kc + 8]);
            }
            #pragma unroll
            for (int i = 0; i < 2; ++i)
                #pragma unroll
                for (int j = 0; j < 8; ++j)
                    asm volatile(
                        "mma.sync.aligned.m16n8k16.row.col.f32.f16.f16.f32 "
                        "{%0,%1,%2,%3}, {%4,%5,%6,%7}, {%8,%9}, {%0,%1,%2,%3};\n"
                        : "+f"(acc[i][j][0]), "+f"(acc[i][j][1]),
                          "+f"(acc[i][j][2]), "+f"(acc[i][j][3])
                        : "r"(a[i][0]), "r"(a[i][1]), "r"(a[i][2]), "r"(a[i][3]),
                          "r"(b[j][0]), "r"(b[j][1]));
        }
    };

    loadG(0);
    storeS(0);
    __syncthreads();

    #pragma unroll 1
    for (int step = 0; step < NSTEP; ++step) {
        const int cur = step & 1;
        if (step + 1 < NSTEP) loadG(step + 1);
        compute(cur);
        if (step + 1 < NSTEP) storeS(cur ^ 1);
        __syncthreads();
    }

    // Epilogue: out NCHW idx = pe + 3136*(255*n + k)
    #pragma unroll
    for (int i = 0; i < 2; ++i) {
        const int kb = k0 + warpM * 32 + i * 16 + g;
        #pragma unroll
        for (int j = 0; j < 8; ++j) {
            const int pc = p0 + warpN * 64 + j * 8 + tg * 2;
            #pragma unroll
            for (int e = 0; e < 2; ++e) {
                const unsigned pe = (unsigned)(pc + e);
                const unsigned nn = pe / HW_;
                out[pe + (size_t)HW_ * (255u * nn + (unsigned)kb)]       = acc[i][j][e];
                out[pe + (size_t)HW_ * (255u * nn + (unsigned)(kb + 8))] = acc[i][j][2 + e];
            }
        }
    }
}

extern "C" void kernel_launch(void* const* d_in, const int* in_sizes, int n_in,
                              void* d_out, int out_size) {
    const float* x   = (const float*)d_in[0];   // (32,128,56,56) f32
    const float* wgt = (const float*)d_in[1];   // (256,128,3,3)  f32

    zero_border_kernel<<<N_ * HP_, 128>>>();
    xform_x_kernel<<<dim3(N_, H_), 256>>>(x);
    quant_w_kernel<<<(K_ * KINP + 255) / 256, 256>>>(wgt);

    dim3 grid(PIX_ / BN, K_ / BM);              // (784, 2)
    conv_mma_kernel<<<grid, 256>>>((float*)d_out);
}

// round 4
// speedup vs baseline: 1.3333x; 1.2402x over previous
#include <cuda_runtime.h>
#include <cuda_fp16.h>
#include <cstdint>

// ---------------- problem constants ----------------
#define N_    32
#define C_    128
#define H_    56
#define W_    56
#define K_    256
#define HW_   3136
#define PIX_  100352
#define KINP  1152      // 128*9
#define HP_   58
#define WP_   58

// ---------------- GEMM tiling ----------------
#define BM    128       // k-out per CTA
#define BN    256       // pixels per CTA
#define BK    64        // k-halves per stage
#define NSTEP 18        // 1152/64
#define PITCH 72        // halves per smem row (BK + 8) -> conflict-free
#define SA_HALVES (BM * PITCH)              // 9216
#define STAGE_HALVES ((BM + BN) * PITCH)    // 27648
#define STAGE_BYTES  (STAGE_HALVES * 2)     // 55296
#define SMEM_TOTAL   (3 * STAGE_BYTES)      // 165888

// ---------------- scratch ----------------
__device__ alignas(1024) __half g_xp[(size_t)N_ * HP_ * WP_ * C_];
__device__ alignas(1024) __half g_wq[K_ * KINP];

// ---------------- helpers ----------------
__device__ __forceinline__ uint32_t smem_u32(const void* p) {
    uint32_t a;
    asm("{ .reg .u64 t; cvta.to.shared.u64 t, %1; cvt.u32.u64 %0, t; }" : "=r"(a) : "l"(p));
    return a;
}
#define CP16(dst, src) \
    asm volatile("cp.async.cg.shared.global [%0], [%1], 16;" :: "r"(dst), "l"(src) : "memory")
#define CP_COMMIT() asm volatile("cp.async.commit_group;" ::: "memory")
#define CP_WAIT1()  asm volatile("cp.async.wait_group 1;" ::: "memory")
#define CP_WAIT0()  asm volatile("cp.async.wait_group 0;" ::: "memory")
#define LDSM_X4(r0, r1, r2, r3, addr) \
    asm volatile("ldmatrix.sync.aligned.m8n8.x4.shared.b16 {%0,%1,%2,%3}, [%4];" \
        : "=r"(r0), "=r"(r1), "=r"(r2), "=r"(r3) : "r"(addr))

__device__ __forceinline__ float quant16f(float x) {
    float r = rintf(x * 4096.0f);
    r = fminf(fmaxf(r, -32768.0f), 32767.0f);
    return r * (1.0f / 4096.0f);
}

// ---------------- prepass kernels (unchanged from R2) ----------------
__global__ void zero_border_kernel() {
    int b = blockIdx.x;              // 32*58
    int n = b / HP_, hp = b % HP_;
    __half* rowp = g_xp + ((size_t)(n * HP_ + hp)) * WP_ * C_;
    uint4 z = make_uint4(0, 0, 0, 0);
    if (hp == 0 || hp == HP_ - 1) {
        for (int i = threadIdx.x; i < WP_ * C_ / 8; i += blockDim.x)
            reinterpret_cast<uint4*>(rowp)[i] = z;
    } else {
        if (threadIdx.x < 32) {
            int side = threadIdx.x >> 4;
            int q    = threadIdx.x & 15;
            __half* colp = rowp + (side ? (size_t)(WP_ - 1) * C_ : 0);
            reinterpret_cast<uint4*>(colp)[q] = z;
        }
    }
}

__global__ void xform_x_kernel(const float* __restrict__ x) {
    __shared__ __half st[W_ * C_];
    const int n = blockIdx.x, h = blockIdx.y;
    const int tid = threadIdx.x;
    const int c  = tid >> 1;
    const int wh = (tid & 1) * 28;
    const float* src = x + ((size_t)(n * C_ + c) * H_ + h) * W_ + wh;
    #pragma unroll
    for (int j = 0; j < 7; ++j) {
        float4 v = *reinterpret_cast<const float4*>(src + 4 * j);
        int wb = wh + 4 * j;
        st[(wb + 0) * C_ + c] = __float2half_rn(quant16f(v.x));
        st[(wb + 1) * C_ + c] = __float2half_rn(quant16f(v.y));
        st[(wb + 2) * C_ + c] = __float2half_rn(quant16f(v.z));
        st[(wb + 3) * C_ + c] = __float2half_rn(quant16f(v.w));
    }
    __syncthreads();
    __half* dst = g_xp + ((size_t)((n * HP_ + h + 1) * WP_ + 1)) * C_;
    for (int idx = tid; idx < W_ * C_ / 8; idx += 256) {
        int w = idx >> 4, q = idx & 15;
        reinterpret_cast<uint4*>(dst + (size_t)w * C_)[q] =
            reinterpret_cast<const uint4*>(st + w * C_)[q];
    }
}

__global__ void quant_w_kernel(const float* __restrict__ w) {
    int idx = blockIdx.x * 256 + threadIdx.x;
    if (idx >= K_ * KINP) return;
    int k = idx / KINP, t = idx % KINP;
    int rs = t >> 7, c = t & 127;
    float v = w[(size_t)(k * C_ + c) * 9 + rs];
    g_wq[idx] = __float2half_rn(quant16f(v));
}

// ---------------- main conv kernel: HMMA + ldmatrix + cp.async ----------------
// grid (392, 2), 512 threads. CTA: 128 k-out x 256 pixels, K loop 18 x BK=64.
__global__ __launch_bounds__(512, 1) void conv_hmma_kernel(float* __restrict__ out) {
    extern __shared__ __align__(128) __half smem[];
    const uint32_t sbase = smem_u32(smem);

    const int tid  = threadIdx.x;
    const int lane = tid & 31;
    const int wid  = tid >> 5;          // 0..15
    const int warpM = wid & 3;          // 4 warps along M (32 rows each)
    const int warpN = wid >> 2;         // 4 warps along N (64 pixels each)
    const int g  = lane >> 2;
    const int tg = lane & 3;

    const int p0 = blockIdx.x * BN;
    const int k0 = blockIdx.y * BM;

    // ---- loader mappings ----
    // A: 128 rows x 8 chunks(16B); 4 thr/row x 2 chunks each
    const int aRow = tid & 127;
    const int ac0  = tid >> 7;                       // chunks ac0, ac0+4
    const __half* aG = g_wq + (size_t)(k0 + aRow) * KINP;
    // B: 256 pixels x 8 chunks; 2 thr/pixel x 4 chunks each
    const int pp  = tid >> 1;
    const int bc0 = (tid & 1) * 4;                   // chunks bc0..bc0+3
    const int bp  = p0 + pp;
    const int bn  = bp / HW_;
    const int bhw = bp % HW_;
    const int bh  = bhw / W_;
    const int bw  = bhw % W_;
    const __half* bG = g_xp + ((size_t)((bn * HP_ + bh) * WP_ + bw)) * C_;

    // ---- fragment ldmatrix base addresses (lane-dependent) ----
    const uint32_t fragSel = ((lane & 15) * PITCH + ((lane >> 4) << 3)) * 2;
    const uint32_t aFragBase = sbase + (uint32_t)(warpM * 32 * PITCH * 2) + fragSel;
    const uint32_t bFragBase = sbase + (uint32_t)(SA_HALVES * 2)
                             + (uint32_t)(warpN * 64 * PITCH * 2) + fragSel;

    float acc[2][8][4];
    #pragma unroll
    for (int i = 0; i < 2; ++i)
        #pragma unroll
        for (int j = 0; j < 8; ++j)
            #pragma unroll
            for (int e = 0; e < 4; ++e) acc[i][j][e] = 0.0f;

    auto load_stage = [&](int s) {
        const int buf = s % 3;
        const uint32_t sA = sbase + buf * STAGE_BYTES;
        const uint32_t sB = sA + SA_HALVES * 2;
        // stage -> (r, s, channel block)
        const int rs = s >> 1;
        const int r  = (rs * 11) >> 5;               // rs/3 for rs<9
        const int ss = rs - 3 * r;
        const int ch = (s & 1) << 6;
        const __half* asrc = aG + s * BK;
        const __half* bsrc = bG + (r * WP_ + ss) * C_ + ch;
        #pragma unroll
        for (int j = 0; j < 2; ++j) {
            const int c = ac0 + 4 * j;
            CP16(sA + (aRow * PITCH + c * 8) * 2, asrc + c * 8);
        }
        #pragma unroll
        for (int j = 0; j < 4; ++j) {
            const int c = bc0 + j;
            CP16(sB + (pp * PITCH + c * 8) * 2, bsrc + c * 8);
        }
    };

    auto compute = [&](int buf) {
        const uint32_t off = buf * STAGE_BYTES;
        #pragma unroll
        for (int kk = 0; kk < 4; ++kk) {
            const uint32_t kcb = kk * 32;            // 16 halves = 32 bytes
            uint32_t a[2][4], b[8][2];
            #pragma unroll
            for (int i = 0; i < 2; ++i)
                LDSM_X4(a[i][0], a[i][1], a[i][2], a[i][3],
                        aFragBase + off + kcb + i * (16 * PITCH * 2));
            #pragma unroll
            for (int jj = 0; jj < 4; ++jj)
                LDSM_X4(b[2 * jj][0], b[2 * jj + 1][0], b[2 * jj][1], b[2 * jj + 1][1],
                        bFragBase + off + kcb + jj * (16 * PITCH * 2));
            #pragma unroll
            for (int i = 0; i < 2; ++i)
                #pragma unroll
                for (int j = 0; j < 8; ++j)
                    asm volatile(
                        "mma.sync.aligned.m16n8k16.row.col.f32.f16.f16.f32 "
                        "{%0,%1,%2,%3}, {%4,%5,%6,%7}, {%8,%9}, {%0,%1,%2,%3};\n"
                        : "+f"(acc[i][j][0]), "+f"(acc[i][j][1]),
                          "+f"(acc[i][j][2]), "+f"(acc[i][j][3])
                        : "r"(a[i][0]), "r"(a[i][1]), "r"(a[i][2]), "r"(a[i][3]),
                          "r"(b[j][0]), "r"(b[j][1]));
        }
    };

    // ---- 3-stage pipeline ----
    load_stage(0); CP_COMMIT();
    load_stage(1); CP_COMMIT();

    #pragma unroll 1
    for (int s = 0; s < NSTEP; ++s) {
        if (s < NSTEP - 1) { CP_WAIT1(); } else { CP_WAIT0(); }
        __syncthreads();                 // stage s visible; buf (s+2)%3 free
        if (s + 2 < NSTEP) { load_stage(s + 2); CP_COMMIT(); }
        compute(s % 3);
    }

    // ---- epilogue: registers -> gmem (NCHW) ----
    #pragma unroll
    for (int i = 0; i < 2; ++i) {
        const int kb = k0 + warpM * 32 + i * 16 + g;
        #pragma unroll
        for (int j = 0; j < 8; ++j) {
            const int pc = p0 + warpN * 64 + j * 8 + tg * 2;
            #pragma unroll
            for (int e = 0; e < 2; ++e) {
                const unsigned pe = (unsigned)(pc + e);
                const unsigned nn = pe / HW_;
                out[pe + (size_t)HW_ * (255u * nn + (unsigned)kb)]       = acc[i][j][e];
                out[pe + (size_t)HW_ * (255u * nn + (unsigned)(kb + 8))] = acc[i][j][2 + e];
            }
        }
    }
}

extern "C" void kernel_launch(void* const* d_in, const int* in_sizes, int n_in,
                              void* d_out, int out_size) {
    const float* x   = (const float*)d_in[0];   // (32,128,56,56) f32
    const float* wgt = (const float*)d_in[1];   // (256,128,3,3)  f32

    zero_border_kernel<<<N_ * HP_, 128>>>();
    xform_x_kernel<<<dim3(N_, H_), 256>>>(x);
    quant_w_kernel<<<(K_ * KINP + 255) / 256, 256>>>(wgt);

    static bool attr_set = false;
    if (!attr_set) {
        cudaFuncSetAttribute(conv_hmma_kernel,
                             cudaFuncAttributeMaxDynamicSharedMemorySize, SMEM_TOTAL);
        attr_set = true;
    }
    dim3 grid(PIX_ / BN, K_ / BM);              // (392, 2)
    conv_hmma_kernel<<<grid, 512, SMEM_TOTAL>>>((float*)d_out);
}